// round 1
// baseline (speedup 1.0000x reference)
#include <cuda_runtime.h>
#include <math.h>

#define S_LEN  3072
#define DIM_   2048
#define NH     16
#define HD     128
#define C_HALF 64          // HD/2
#define GF 8
#define GH 16
#define GW 24
#define CF 22              // C_HALF - 2*(C_HALF/3)
#define CH 21

// ---------------- scratch (device globals; no allocation allowed) -------------
__device__ float g_Q[(size_t)S_LEN * DIM_];
__device__ float g_K[(size_t)S_LEN * DIM_];
__device__ float g_V[(size_t)S_LEN * DIM_];
__device__ float g_O[(size_t)S_LEN * DIM_];
__device__ float g_S[(size_t)NH * S_LEN * S_LEN];   // 604 MB scores/probs
__device__ float g_cos[S_LEN * C_HALF];
__device__ float g_sin[S_LEN * C_HALF];

// ---------------- RoPE angle table ------------------------------------------
__global__ void rope_table_kernel(const float* __restrict__ fa,
                                  float* __restrict__ ctab,
                                  float* __restrict__ stab) {
    int idx = blockIdx.x * blockDim.x + threadIdx.x;
    if (idx >= S_LEN * C_HALF) return;
    int s = idx >> 6;          // / 64
    int j = idx & 63;
    int f = s / (GH * GW);
    int h = (s / GW) % GH;
    int w = s % GW;
    int row = (j < CF) ? f : (j < CF + CH) ? h : w;
    float a = fa[row * C_HALF + j];
    ctab[idx] = cosf(a);
    stab[idx] = sinf(a);
}

// ---------------- fused RMSNorm (over DIM) + RoPE ----------------------------
__global__ void rms_rope_kernel(float* __restrict__ buf,
                                const float* __restrict__ g,
                                const float* __restrict__ ctab,
                                const float* __restrict__ stab) {
    int s = blockIdx.x;
    float* row = buf + (size_t)s * DIM_;
    int tid = threadIdx.x;

    float ss = 0.f;
    #pragma unroll
    for (int i = tid; i < DIM_; i += 256) {
        float v = row[i];
        ss += v * v;
    }
    __shared__ float red[256];
    red[tid] = ss;
    __syncthreads();
    #pragma unroll
    for (int off = 128; off > 0; off >>= 1) {
        if (tid < off) red[tid] += red[tid + off];
        __syncthreads();
    }
    float inv = rsqrtf(red[0] * (1.0f / DIM_) + 1e-6f);

    const float* crow = ctab + s * C_HALF;
    const float* srow = stab + s * C_HALF;
    #pragma unroll
    for (int p = tid; p < DIM_ / 2; p += 256) {
        int j = p & (C_HALF - 1);
        float c = crow[j], sn = srow[j];
        float te = row[2 * p]     * inv * g[2 * p];
        float to = row[2 * p + 1] * inv * g[2 * p + 1];
        row[2 * p]     = te * c - to * sn;
        row[2 * p + 1] = te * sn + to * c;
    }
}

// ---------------- GEMM NT: C = alpha * A(MxK,lda) * B(NxK,ldb)^T + bias ------
__global__ __launch_bounds__(256)
void gemm_nt_kernel(const float* __restrict__ A, const float* __restrict__ B,
                    float* __restrict__ C, const float* __restrict__ bias,
                    int M, int N, int K, int lda, int ldb, int ldc,
                    long long sA, long long sB, long long sC, float alpha) {
    __shared__ float As[16][132];
    __shared__ float Bs[16][132];
    A += (long long)blockIdx.z * sA;
    B += (long long)blockIdx.z * sB;
    C += (long long)blockIdx.z * sC;
    int m0 = blockIdx.y * 128, n0 = blockIdx.x * 128;
    int tid = threadIdx.x;
    int tx = tid & 15, ty = tid >> 4;

    float acc[8][8];
    #pragma unroll
    for (int i = 0; i < 8; ++i)
        #pragma unroll
        for (int j = 0; j < 8; ++j) acc[i][j] = 0.f;

    for (int k0 = 0; k0 < K; k0 += 16) {
        #pragma unroll
        for (int l = 0; l < 2; ++l) {
            int idx = tid + l * 256;
            int row = idx >> 2, kc = (idx & 3) << 2;
            float4 v = *(const float4*)&A[(long long)(m0 + row) * lda + k0 + kc];
            As[kc + 0][row] = v.x; As[kc + 1][row] = v.y;
            As[kc + 2][row] = v.z; As[kc + 3][row] = v.w;
        }
        #pragma unroll
        for (int l = 0; l < 2; ++l) {
            int idx = tid + l * 256;
            int row = idx >> 2, kc = (idx & 3) << 2;
            float4 v = *(const float4*)&B[(long long)(n0 + row) * ldb + k0 + kc];
            Bs[kc + 0][row] = v.x; Bs[kc + 1][row] = v.y;
            Bs[kc + 2][row] = v.z; Bs[kc + 3][row] = v.w;
        }
        __syncthreads();
        #pragma unroll
        for (int kk = 0; kk < 16; ++kk) {
            float a[8], b[8];
            *(float4*)&a[0] = *(const float4*)&As[kk][ty * 8];
            *(float4*)&a[4] = *(const float4*)&As[kk][ty * 8 + 4];
            *(float4*)&b[0] = *(const float4*)&Bs[kk][tx * 8];
            *(float4*)&b[4] = *(const float4*)&Bs[kk][tx * 8 + 4];
            #pragma unroll
            for (int i = 0; i < 8; ++i)
                #pragma unroll
                for (int j = 0; j < 8; ++j)
                    acc[i][j] = fmaf(a[i], b[j], acc[i][j]);
        }
        __syncthreads();
    }

    #pragma unroll
    for (int i = 0; i < 8; ++i) {
        float out[8];
        #pragma unroll
        for (int j = 0; j < 8; ++j) {
            float v = acc[i][j] * alpha;
            if (bias) v += bias[n0 + tx * 8 + j];
            out[j] = v;
        }
        float* cp = &C[(long long)(m0 + ty * 8 + i) * ldc + n0 + tx * 8];
        *(float4*)&cp[0] = *(float4*)&out[0];
        *(float4*)&cp[4] = *(float4*)&out[4];
    }
}

// ---------------- GEMM NN: C = A(MxK,lda) * B(KxN,ldb) -----------------------
__global__ __launch_bounds__(256)
void gemm_nn_kernel(const float* __restrict__ A, const float* __restrict__ B,
                    float* __restrict__ C,
                    int M, int N, int K, int lda, int ldb, int ldc,
                    long long sA, long long sB, long long sC) {
    __shared__ float As[16][132];
    __shared__ float Bs[16][132];
    A += (long long)blockIdx.z * sA;
    B += (long long)blockIdx.z * sB;
    C += (long long)blockIdx.z * sC;
    int m0 = blockIdx.y * 128, n0 = blockIdx.x * 128;
    int tid = threadIdx.x;
    int tx = tid & 15, ty = tid >> 4;

    float acc[8][8];
    #pragma unroll
    for (int i = 0; i < 8; ++i)
        #pragma unroll
        for (int j = 0; j < 8; ++j) acc[i][j] = 0.f;

    for (int k0 = 0; k0 < K; k0 += 16) {
        #pragma unroll
        for (int l = 0; l < 2; ++l) {
            int idx = tid + l * 256;
            int row = idx >> 2, kc = (idx & 3) << 2;
            float4 v = *(const float4*)&A[(long long)(m0 + row) * lda + k0 + kc];
            As[kc + 0][row] = v.x; As[kc + 1][row] = v.y;
            As[kc + 2][row] = v.z; As[kc + 3][row] = v.w;
        }
        #pragma unroll
        for (int l = 0; l < 2; ++l) {
            int idx = tid + l * 256;
            int row = idx >> 5;            // k within tile (0..15)
            int cg  = idx & 31;            // column group of 4
            float4 v = *(const float4*)&B[(long long)(k0 + row) * ldb + n0 + cg * 4];
            *(float4*)&Bs[row][cg * 4] = v;
        }
        __syncthreads();
        #pragma unroll
        for (int kk = 0; kk < 16; ++kk) {
            float a[8], b[8];
            *(float4*)&a[0] = *(const float4*)&As[kk][ty * 8];
            *(float4*)&a[4] = *(const float4*)&As[kk][ty * 8 + 4];
            *(float4*)&b[0] = *(const float4*)&Bs[kk][tx * 8];
            *(float4*)&b[4] = *(const float4*)&Bs[kk][tx * 8 + 4];
            #pragma unroll
            for (int i = 0; i < 8; ++i)
                #pragma unroll
                for (int j = 0; j < 8; ++j)
                    acc[i][j] = fmaf(a[i], b[j], acc[i][j]);
        }
        __syncthreads();
    }

    #pragma unroll
    for (int i = 0; i < 8; ++i) {
        float* cp = &C[(long long)(m0 + ty * 8 + i) * ldc + n0 + tx * 8];
        *(float4*)&cp[0] = *(float4*)&acc[i][0];
        *(float4*)&cp[4] = *(float4*)&acc[i][4];
    }
}

// ---------------- row softmax over S_LEN columns -----------------------------
__global__ void softmax_kernel(float* __restrict__ S) {
    size_t r = blockIdx.x;
    float* row = S + r * S_LEN;
    int tid = threadIdx.x;

    float vals[S_LEN / 256];
    float mx = -INFINITY;
    #pragma unroll
    for (int i = 0; i < S_LEN / 256; ++i) {
        vals[i] = row[tid + i * 256];
        mx = fmaxf(mx, vals[i]);
    }
    __shared__ float red[256];
    red[tid] = mx;
    __syncthreads();
    #pragma unroll
    for (int off = 128; off > 0; off >>= 1) {
        if (tid < off) red[tid] = fmaxf(red[tid], red[tid + off]);
        __syncthreads();
    }
    mx = red[0];
    __syncthreads();

    float sum = 0.f;
    #pragma unroll
    for (int i = 0; i < S_LEN / 256; ++i) {
        vals[i] = __expf(vals[i] - mx);
        sum += vals[i];
    }
    red[tid] = sum;
    __syncthreads();
    #pragma unroll
    for (int off = 128; off > 0; off >>= 1) {
        if (tid < off) red[tid] += red[tid + off];
        __syncthreads();
    }
    float inv = 1.0f / red[0];
    #pragma unroll
    for (int i = 0; i < S_LEN / 256; ++i)
        row[tid + i * 256] = vals[i] * inv;
}

// ---------------- launch ------------------------------------------------------
extern "C" void kernel_launch(void* const* d_in, const int* in_sizes, int n_in,
                              void* d_out, int out_size) {
    const float* x   = (const float*)d_in[0];
    const float* fa  = (const float*)d_in[1];
    const float* Wq  = (const float*)d_in[2];
    const float* bq  = (const float*)d_in[3];
    const float* Wk  = (const float*)d_in[4];
    const float* bk  = (const float*)d_in[5];
    const float* Wv  = (const float*)d_in[6];
    const float* bv  = (const float*)d_in[7];
    const float* Wo  = (const float*)d_in[8];
    const float* bo  = (const float*)d_in[9];
    const float* gq  = (const float*)d_in[10];
    const float* gk  = (const float*)d_in[11];
    float* out = (float*)d_out;

    float *Qp, *Kp, *Vp, *Op, *Sp, *Cp, *Sn;
    cudaGetSymbolAddress((void**)&Qp, g_Q);
    cudaGetSymbolAddress((void**)&Kp, g_K);
    cudaGetSymbolAddress((void**)&Vp, g_V);
    cudaGetSymbolAddress((void**)&Op, g_O);
    cudaGetSymbolAddress((void**)&Sp, g_S);
    cudaGetSymbolAddress((void**)&Cp, g_cos);
    cudaGetSymbolAddress((void**)&Sn, g_sin);

    // RoPE tables
    rope_table_kernel<<<(S_LEN * C_HALF + 255) / 256, 256>>>(fa, Cp, Sn);

    // QKV projections: (3072x2048) = x (3072x2048) @ W^T
    dim3 gProj(DIM_ / 128, S_LEN / 128, 1);
    gemm_nt_kernel<<<gProj, 256>>>(x, Wq, Qp, bq, S_LEN, DIM_, DIM_,
                                   DIM_, DIM_, DIM_, 0, 0, 0, 1.0f);
    gemm_nt_kernel<<<gProj, 256>>>(x, Wk, Kp, bk, S_LEN, DIM_, DIM_,
                                   DIM_, DIM_, DIM_, 0, 0, 0, 1.0f);
    gemm_nt_kernel<<<gProj, 256>>>(x, Wv, Vp, bv, S_LEN, DIM_, DIM_,
                                   DIM_, DIM_, DIM_, 0, 0, 0, 1.0f);

    // RMSNorm + RoPE on Q and K
    rms_rope_kernel<<<S_LEN, 256>>>(Qp, gq, Cp, Sn);
    rms_rope_kernel<<<S_LEN, 256>>>(Kp, gk, Cp, Sn);

    // scores[h] = scale * Q_h @ K_h^T   (batched over heads via z)
    const float scale = 0.08838834764831845f;  // 1/sqrt(128)
    dim3 gScore(S_LEN / 128, S_LEN / 128, NH);
    gemm_nt_kernel<<<gScore, 256>>>(Qp, Kp, Sp, nullptr, S_LEN, S_LEN, HD,
                                    DIM_, DIM_, S_LEN,
                                    (long long)HD, (long long)HD,
                                    (long long)S_LEN * S_LEN, scale);

    // softmax rows
    softmax_kernel<<<NH * S_LEN, 256>>>(Sp);

    // O[h] = P_h @ V_h  (NN)
    dim3 gPV(HD / 128, S_LEN / 128, NH);
    gemm_nn_kernel<<<gPV, 256>>>(Sp, Vp, Op, S_LEN, HD, S_LEN,
                                 S_LEN, DIM_, DIM_,
                                 (long long)S_LEN * S_LEN, (long long)HD,
                                 (long long)HD);

    // out = O @ Wo^T + bo
    gemm_nt_kernel<<<gProj, 256>>>(Op, Wo, out, bo, S_LEN, DIM_, DIM_,
                                   DIM_, DIM_, DIM_, 0, 0, 0, 1.0f);
}

// round 3
// speedup vs baseline: 1.3374x; 1.3374x over previous
#include <cuda_runtime.h>
#include <mma.h>
#include <math.h>

using namespace nvcuda;

#define S_LEN  3072
#define DIM_   2048
#define NH     16
#define HD     128
#define C_HALF 64
#define GF 8
#define GH 16
#define GW 24
#define CF 22
#define CH 21
#define LDT 40   // shared tile leading dim (32 + 8 pad)

// ---------------- scratch ----------------------------------------------------
__device__ float g_Q[(size_t)S_LEN * DIM_];
__device__ float g_K[(size_t)S_LEN * DIM_];
__device__ float g_V[(size_t)S_LEN * DIM_];
__device__ float g_Vt[(size_t)DIM_ * S_LEN];        // per-head transposed V
__device__ float g_O[(size_t)S_LEN * DIM_];
__device__ float g_S[(size_t)NH * S_LEN * S_LEN];   // 604 MB scores/probs
__device__ float g_cos[S_LEN * C_HALF];
__device__ float g_sin[S_LEN * C_HALF];

// ---------------- RoPE angle table ------------------------------------------
__global__ void rope_table_kernel(const float* __restrict__ fa,
                                  float* __restrict__ ctab,
                                  float* __restrict__ stab) {
    int idx = blockIdx.x * blockDim.x + threadIdx.x;
    if (idx >= S_LEN * C_HALF) return;
    int s = idx >> 6;
    int j = idx & 63;
    int f = s / (GH * GW);
    int h = (s / GW) % GH;
    int w = s % GW;
    int row = (j < CF) ? f : (j < CF + CH) ? h : w;
    float a = fa[row * C_HALF + j];
    ctab[idx] = cosf(a);
    stab[idx] = sinf(a);
}

// ---------------- fused RMSNorm (over DIM) + RoPE ----------------------------
__global__ void rms_rope_kernel(float* __restrict__ buf,
                                const float* __restrict__ g,
                                const float* __restrict__ ctab,
                                const float* __restrict__ stab) {
    int s = blockIdx.x;
    float* row = buf + (size_t)s * DIM_;
    int tid = threadIdx.x;

    float ss = 0.f;
    #pragma unroll
    for (int i = tid; i < DIM_; i += 256) {
        float v = row[i];
        ss += v * v;
    }
    __shared__ float red[256];
    red[tid] = ss;
    __syncthreads();
    #pragma unroll
    for (int off = 128; off > 0; off >>= 1) {
        if (tid < off) red[tid] += red[tid + off];
        __syncthreads();
    }
    float inv = rsqrtf(red[0] * (1.0f / DIM_) + 1e-6f);

    const float* crow = ctab + s * C_HALF;
    const float* srow = stab + s * C_HALF;
    #pragma unroll
    for (int p = tid; p < DIM_ / 2; p += 256) {
        int j = p & (C_HALF - 1);
        float c = crow[j], sn = srow[j];
        float te = row[2 * p]     * inv * g[2 * p];
        float to = row[2 * p + 1] * inv * g[2 * p + 1];
        row[2 * p]     = te * c - to * sn;
        row[2 * p + 1] = te * sn + to * c;
    }
}

// ---------------- V transpose: Vt[c][s] = V[s][c] ----------------------------
__global__ void transpose_kernel(const float* __restrict__ in,
                                 float* __restrict__ out) {
    __shared__ float t[32][33];
    int c0 = blockIdx.x * 32;
    int s0 = blockIdx.y * 32;
    int tx = threadIdx.x, ty = threadIdx.y;
    #pragma unroll
    for (int r = 0; r < 32; r += 8)
        t[ty + r][tx] = in[(size_t)(s0 + ty + r) * DIM_ + c0 + tx];
    __syncthreads();
    #pragma unroll
    for (int r = 0; r < 32; r += 8)
        out[(size_t)(c0 + ty + r) * S_LEN + s0 + tx] = t[tx][ty + r];
}

// ---------------- tf32 tensor-core GEMM NT -----------------------------------
// C = alpha * A(MxK, lda) @ B(NxK, ldb)^T + bias
// block tile 128x128, k-step 32, 8 warps (4 m x 2 n), warp tile 32x64
__global__ __launch_bounds__(256)
void gemm_nt_tc(const float* __restrict__ A, const float* __restrict__ B,
                float* __restrict__ C, const float* __restrict__ bias,
                int K, int lda, int ldb, int ldc,
                long long sA, long long sB, long long sC, float alpha) {
    __shared__ float sh[2 * 128 * LDT];
    float* As = sh;
    float* Bs = sh + 128 * LDT;

    A += (long long)blockIdx.z * sA;
    B += (long long)blockIdx.z * sB;
    C += (long long)blockIdx.z * sC;
    int m0 = blockIdx.y * 128, n0 = blockIdx.x * 128;
    int tid = threadIdx.x;
    int w = tid >> 5, lane = tid & 31;
    int wm = w & 3, wn = w >> 2;

    wmma::fragment<wmma::accumulator, 16, 16, 8, float> cf[2][4];
    #pragma unroll
    for (int i = 0; i < 2; ++i)
        #pragma unroll
        for (int j = 0; j < 4; ++j) wmma::fill_fragment(cf[i][j], 0.f);

    for (int k0 = 0; k0 < K; k0 += 32) {
        // A tile 128x32 (alpha folded in)
        #pragma unroll
        for (int l = 0; l < 4; ++l) {
            int idx = tid + l * 256;
            int row = idx >> 3, kc = (idx & 7) << 2;
            float4 v = *(const float4*)&A[(long long)(m0 + row) * lda + k0 + kc];
            float* p = &As[row * LDT + kc];
            p[0] = v.x * alpha; p[1] = v.y * alpha;
            p[2] = v.z * alpha; p[3] = v.w * alpha;
        }
        // B tile 128x32
        #pragma unroll
        for (int l = 0; l < 4; ++l) {
            int idx = tid + l * 256;
            int row = idx >> 3, kc = (idx & 7) << 2;
            float4 v = *(const float4*)&B[(long long)(n0 + row) * ldb + k0 + kc];
            float* p = &Bs[row * LDT + kc];
            p[0] = v.x; p[1] = v.y; p[2] = v.z; p[3] = v.w;
        }
        __syncthreads();

        #pragma unroll
        for (int kk = 0; kk < 32; kk += 8) {
            wmma::fragment<wmma::matrix_a, 16, 16, 8, wmma::precision::tf32,
                           wmma::row_major> af[2];
            wmma::fragment<wmma::matrix_b, 16, 16, 8, wmma::precision::tf32,
                           wmma::col_major> bf[4];
            #pragma unroll
            for (int i = 0; i < 2; ++i) {
                wmma::load_matrix_sync(af[i], &As[(wm * 32 + i * 16) * LDT + kk], LDT);
                #pragma unroll
                for (int t = 0; t < af[i].num_elements; ++t)
                    af[i].x[t] = wmma::__float_to_tf32(af[i].x[t]);
            }
            #pragma unroll
            for (int j = 0; j < 4; ++j) {
                wmma::load_matrix_sync(bf[j], &Bs[(wn * 64 + j * 16) * LDT + kk], LDT);
                #pragma unroll
                for (int t = 0; t < bf[j].num_elements; ++t)
                    bf[j].x[t] = wmma::__float_to_tf32(bf[j].x[t]);
            }
            #pragma unroll
            for (int i = 0; i < 2; ++i)
                #pragma unroll
                for (int j = 0; j < 4; ++j)
                    wmma::mma_sync(cf[i][j], af[i], bf[j], cf[i][j]);
        }
        __syncthreads();
    }

    // epilogue: stage per-warp 16x64 slabs in shared, add bias, write coalesced
    float* stage = sh + w * 1024;
    #pragma unroll
    for (int i = 0; i < 2; ++i) {
        #pragma unroll
        for (int j = 0; j < 4; ++j)
            wmma::store_matrix_sync(stage + j * 16, cf[i][j], 64, wmma::mem_row_major);
        __syncwarp();
        #pragma unroll
        for (int t = lane; t < 256; t += 32) {
            int row = t >> 4, c4 = (t & 15) << 2;
            float4 v = *(float4*)&stage[row * 64 + c4];
            if (bias) {
                int nb = n0 + wn * 64 + c4;
                v.x += bias[nb + 0]; v.y += bias[nb + 1];
                v.z += bias[nb + 2]; v.w += bias[nb + 3];
            }
            *(float4*)&C[(long long)(m0 + wm * 32 + i * 16 + row) * ldc +
                         n0 + wn * 64 + c4] = v;
        }
        __syncwarp();
    }
}

// ---------------- row softmax over S_LEN columns -----------------------------
__global__ void softmax_kernel(float* __restrict__ S) {
    size_t r = blockIdx.x;
    float* row = S + r * S_LEN;
    int tid = threadIdx.x;

    float vals[S_LEN / 256];
    float mx = -INFINITY;
    #pragma unroll
    for (int i = 0; i < S_LEN / 256; ++i) {
        vals[i] = row[tid + i * 256];
        mx = fmaxf(mx, vals[i]);
    }
    __shared__ float red[256];
    red[tid] = mx;
    __syncthreads();
    #pragma unroll
    for (int off = 128; off > 0; off >>= 1) {
        if (tid < off) red[tid] = fmaxf(red[tid], red[tid + off]);
        __syncthreads();
    }
    mx = red[0];
    __syncthreads();

    float sum = 0.f;
    #pragma unroll
    for (int i = 0; i < S_LEN / 256; ++i) {
        vals[i] = __expf(vals[i] - mx);
        sum += vals[i];
    }
    red[tid] = sum;
    __syncthreads();
    #pragma unroll
    for (int off = 128; off > 0; off >>= 1) {
        if (tid < off) red[tid] += red[tid + off];
        __syncthreads();
    }
    float inv = 1.0f / red[0];
    #pragma unroll
    for (int i = 0; i < S_LEN / 256; ++i)
        row[tid + i * 256] = vals[i] * inv;
}

// ---------------- launch ------------------------------------------------------
extern "C" void kernel_launch(void* const* d_in, const int* in_sizes, int n_in,
                              void* d_out, int out_size) {
    const float* x   = (const float*)d_in[0];
    const float* fa  = (const float*)d_in[1];
    const float* Wq  = (const float*)d_in[2];
    const float* bq  = (const float*)d_in[3];
    const float* Wk  = (const float*)d_in[4];
    const float* bk  = (const float*)d_in[5];
    const float* Wv  = (const float*)d_in[6];
    const float* bv  = (const float*)d_in[7];
    const float* Wo  = (const float*)d_in[8];
    const float* bo  = (const float*)d_in[9];
    const float* gq  = (const float*)d_in[10];
    const float* gk  = (const float*)d_in[11];
    float* out = (float*)d_out;

    float *Qp, *Kp, *Vp, *Vtp, *Op, *Sp, *Cp, *Sn;
    cudaGetSymbolAddress((void**)&Qp, g_Q);
    cudaGetSymbolAddress((void**)&Kp, g_K);
    cudaGetSymbolAddress((void**)&Vp, g_V);
    cudaGetSymbolAddress((void**)&Vtp, g_Vt);
    cudaGetSymbolAddress((void**)&Op, g_O);
    cudaGetSymbolAddress((void**)&Sp, g_S);
    cudaGetSymbolAddress((void**)&Cp, g_cos);
    cudaGetSymbolAddress((void**)&Sn, g_sin);

    rope_table_kernel<<<(S_LEN * C_HALF + 255) / 256, 256>>>(fa, Cp, Sn);

    // QKV projections
    dim3 gProj(DIM_ / 128, S_LEN / 128, 1);
    gemm_nt_tc<<<gProj, 256>>>(x, Wq, Qp, bq, DIM_, DIM_, DIM_, DIM_,
                               0, 0, 0, 1.0f);
    gemm_nt_tc<<<gProj, 256>>>(x, Wk, Kp, bk, DIM_, DIM_, DIM_, DIM_,
                               0, 0, 0, 1.0f);
    gemm_nt_tc<<<gProj, 256>>>(x, Wv, Vp, bv, DIM_, DIM_, DIM_, DIM_,
                               0, 0, 0, 1.0f);

    // RMSNorm + RoPE on Q and K
    rms_rope_kernel<<<S_LEN, 256>>>(Qp, gq, Cp, Sn);
    rms_rope_kernel<<<S_LEN, 256>>>(Kp, gk, Cp, Sn);

    // transpose V (per-head rows become contiguous K-major rows)
    transpose_kernel<<<dim3(DIM_ / 32, S_LEN / 32), dim3(32, 8)>>>(Vp, Vtp);

    // scores[h] = scale * Q_h @ K_h^T
    const float scale = 0.08838834764831845f;
    dim3 gScore(S_LEN / 128, S_LEN / 128, NH);
    gemm_nt_tc<<<gScore, 256>>>(Qp, Kp, Sp, nullptr, HD, DIM_, DIM_, S_LEN,
                                (long long)HD, (long long)HD,
                                (long long)S_LEN * S_LEN, scale);

    // softmax rows
    softmax_kernel<<<NH * S_LEN, 256>>>(Sp);

    // O[h] = P_h @ Vt_h^T   (NT now: Vt_h is 128 x 3072)
    dim3 gPV(HD / 128, S_LEN / 128, NH);
    gemm_nt_tc<<<gPV, 256>>>(Sp, Vtp, Op, nullptr, S_LEN, S_LEN, S_LEN, DIM_,
                             (long long)S_LEN * S_LEN,
                             (long long)HD * S_LEN, (long long)HD, 1.0f);

    // out = O @ Wo^T + bo
    gemm_nt_tc<<<gProj, 256>>>(Op, Wo, out, bo, DIM_, DIM_, DIM_, DIM_,
                               0, 0, 0, 1.0f);
}

// round 4
// speedup vs baseline: 4.0238x; 3.0087x over previous
#include <cuda_runtime.h>
#include <cuda_fp16.h>
#include <mma.h>
#include <math.h>

using namespace nvcuda;

#define S_LEN  3072
#define DIM_   2048
#define NH     16
#define HD     128
#define C_HALF 64
#define GF 8
#define GH 16
#define GW 24
#define CF 22
#define CH 21
#define LDH 40   // half-tile leading dim (32 + 8 pad)

// ---------------- scratch ----------------------------------------------------
__device__ float  g_Q[(size_t)S_LEN * DIM_];
__device__ float  g_K[(size_t)S_LEN * DIM_];
__device__ float  g_V[(size_t)S_LEN * DIM_];
__device__ float  g_S[(size_t)NH * S_LEN * S_LEN];     // fp32 scores
__device__ __half g_xh[(size_t)S_LEN * DIM_];
__device__ __half g_Wqh[(size_t)DIM_ * DIM_];
__device__ __half g_Wkh[(size_t)DIM_ * DIM_];
__device__ __half g_Wvh[(size_t)DIM_ * DIM_];
__device__ __half g_Woh[(size_t)DIM_ * DIM_];
__device__ __half g_Qh[(size_t)S_LEN * DIM_];
__device__ __half g_Kh[(size_t)S_LEN * DIM_];
__device__ __half g_Vth[(size_t)DIM_ * S_LEN];         // transposed V, half
__device__ __half g_Ph[(size_t)NH * S_LEN * S_LEN];    // half probs
__device__ __half g_Oh[(size_t)S_LEN * DIM_];
__device__ float  g_cos[S_LEN * C_HALF];
__device__ float  g_sin[S_LEN * C_HALF];

// ---------------- float -> half convert --------------------------------------
__global__ void f2h_kernel(const float* __restrict__ in,
                           __half* __restrict__ out, int n4) {
    int i = blockIdx.x * blockDim.x + threadIdx.x;
    if (i >= n4) return;
    float4 v = ((const float4*)in)[i];
    ((half2*)out)[2 * i]     = __floats2half2_rn(v.x, v.y);
    ((half2*)out)[2 * i + 1] = __floats2half2_rn(v.z, v.w);
}

// ---------------- RoPE angle table ------------------------------------------
__global__ void rope_table_kernel(const float* __restrict__ fa,
                                  float* __restrict__ ctab,
                                  float* __restrict__ stab) {
    int idx = blockIdx.x * blockDim.x + threadIdx.x;
    if (idx >= S_LEN * C_HALF) return;
    int s = idx >> 6;
    int j = idx & 63;
    int f = s / (GH * GW);
    int h = (s / GW) % GH;
    int w = s % GW;
    int row = (j < CF) ? f : (j < CF + CH) ? h : w;
    float a = fa[row * C_HALF + j];
    ctab[idx] = cosf(a);
    stab[idx] = sinf(a);
}

// ---------------- fused RMSNorm + RoPE, fp32 in -> half out ------------------
__global__ void rms_rope_kernel(const float* __restrict__ in,
                                __half* __restrict__ out,
                                const float* __restrict__ g,
                                const float* __restrict__ ctab,
                                const float* __restrict__ stab) {
    int s = blockIdx.x;
    const float* row = in + (size_t)s * DIM_;
    half2* orow = (half2*)(out + (size_t)s * DIM_);
    int tid = threadIdx.x;

    float ss = 0.f;
    #pragma unroll
    for (int i = tid; i < DIM_; i += 256) {
        float v = row[i];
        ss += v * v;
    }
    __shared__ float red[256];
    red[tid] = ss;
    __syncthreads();
    #pragma unroll
    for (int off = 128; off > 0; off >>= 1) {
        if (tid < off) red[tid] += red[tid + off];
        __syncthreads();
    }
    float inv = rsqrtf(red[0] * (1.0f / DIM_) + 1e-6f);

    const float* crow = ctab + s * C_HALF;
    const float* srow = stab + s * C_HALF;
    #pragma unroll
    for (int p = tid; p < DIM_ / 2; p += 256) {
        int j = p & (C_HALF - 1);
        float c = crow[j], sn = srow[j];
        float te = row[2 * p]     * inv * g[2 * p];
        float to = row[2 * p + 1] * inv * g[2 * p + 1];
        orow[p] = __floats2half2_rn(te * c - to * sn, te * sn + to * c);
    }
}

// ---------------- V transpose fp32 -> half: Vt[c][s] = V[s][c] ---------------
__global__ void transpose_kernel(const float* __restrict__ in,
                                 __half* __restrict__ out) {
    __shared__ float t[32][33];
    int c0 = blockIdx.x * 32;
    int s0 = blockIdx.y * 32;
    int tx = threadIdx.x, ty = threadIdx.y;
    #pragma unroll
    for (int r = 0; r < 32; r += 8)
        t[ty + r][tx] = in[(size_t)(s0 + ty + r) * DIM_ + c0 + tx];
    __syncthreads();
    #pragma unroll
    for (int r = 0; r < 32; r += 8)
        out[(size_t)(c0 + ty + r) * S_LEN + s0 + tx] =
            __float2half_rn(t[tx][ty + r]);
}

// ---------------- cp.async helpers -------------------------------------------
__device__ __forceinline__ void cp_async16(void* smem, const void* gmem) {
    unsigned s = (unsigned)__cvta_generic_to_shared(smem);
    asm volatile("cp.async.cg.shared.global [%0], [%1], 16;\n"
                 :: "r"(s), "l"(gmem));
}
__device__ __forceinline__ void cp_commit() {
    asm volatile("cp.async.commit_group;\n");
}
template <int N>
__device__ __forceinline__ void cp_wait() {
    asm volatile("cp.async.wait_group %0;\n" :: "n"(N));
}

// ---------------- fp16 tensor-core GEMM NT, cp.async double-buffered ---------
// C = alpha * A(MxK, lda) @ B(NxK, ldb)^T + bias
// block 128x128, k-step 32, 16 warps (4x4), warp tile 32x32
template <typename OutT>
__global__ __launch_bounds__(512, 1)
void gemm_nt_h(const __half* __restrict__ A, const __half* __restrict__ B,
               OutT* __restrict__ C, const float* __restrict__ bias,
               int K, int lda, int ldb, int ldc,
               long long sA, long long sB, long long sC, float alpha) {
    __shared__ __half sh[2][2][128 * LDH];   // [stage][A/B][...]

    A += (long long)blockIdx.z * sA;
    B += (long long)blockIdx.z * sB;
    C += (long long)blockIdx.z * sC;
    int m0 = blockIdx.y * 128, n0 = blockIdx.x * 128;
    int tid = threadIdx.x;
    int w = tid >> 5, lane = tid & 31;
    int wm = w & 3, wn = w >> 2;

    // per-thread load slot: row 0..127, 16B chunk 0..3 (8 halfs)
    int lrow = tid >> 2, lch = (tid & 3) << 3;
    const __half* gA = A + (long long)(m0 + lrow) * lda + lch;
    const __half* gB = B + (long long)(n0 + lrow) * ldb + lch;
    __half* sAslot0 = &sh[0][0][lrow * LDH + lch];
    __half* sBslot0 = &sh[0][1][lrow * LDH + lch];
    __half* sAslot1 = &sh[1][0][lrow * LDH + lch];
    __half* sBslot1 = &sh[1][1][lrow * LDH + lch];

    wmma::fragment<wmma::accumulator, 16, 16, 16, float> cf[2][2];
    #pragma unroll
    for (int i = 0; i < 2; ++i)
        #pragma unroll
        for (int j = 0; j < 2; ++j) wmma::fill_fragment(cf[i][j], 0.f);

    int nk = K >> 5;
    // prologue: stage 0
    cp_async16(sAslot0, gA);
    cp_async16(sBslot0, gB);
    cp_commit();

    for (int it = 0; it < nk; ++it) {
        if (it + 1 < nk) {
            int koff = (it + 1) << 5;
            if ((it + 1) & 1) {
                cp_async16(sAslot1, gA + koff);
                cp_async16(sBslot1, gB + koff);
            } else {
                cp_async16(sAslot0, gA + koff);
                cp_async16(sBslot0, gB + koff);
            }
            cp_commit();
            cp_wait<1>();
        } else {
            cp_wait<0>();
        }
        __syncthreads();

        const __half* As = sh[it & 1][0];
        const __half* Bs = sh[it & 1][1];
        #pragma unroll
        for (int kk = 0; kk < 32; kk += 16) {
            wmma::fragment<wmma::matrix_a, 16, 16, 16, __half,
                           wmma::row_major> af[2];
            wmma::fragment<wmma::matrix_b, 16, 16, 16, __half,
                           wmma::col_major> bf[2];
            #pragma unroll
            for (int i = 0; i < 2; ++i)
                wmma::load_matrix_sync(af[i],
                    &As[(wm * 32 + i * 16) * LDH + kk], LDH);
            #pragma unroll
            for (int j = 0; j < 2; ++j)
                wmma::load_matrix_sync(bf[j],
                    &Bs[(wn * 32 + j * 16) * LDH + kk], LDH);
            #pragma unroll
            for (int i = 0; i < 2; ++i)
                #pragma unroll
                for (int j = 0; j < 2; ++j)
                    wmma::mma_sync(cf[i][j], af[i], bf[j], cf[i][j]);
        }
        __syncthreads();
    }

    // epilogue: stage each 16x16 through smem, alpha+bias, vector write
    float* stage = reinterpret_cast<float*>(&sh[0][0][0]) + w * 256;
    int erow = lane >> 1, ec0 = (lane & 1) << 3;
    #pragma unroll
    for (int i = 0; i < 2; ++i) {
        #pragma unroll
        for (int j = 0; j < 2; ++j) {
            wmma::store_matrix_sync(stage, cf[i][j], 16, wmma::mem_row_major);
            __syncwarp();
            const float* sp = stage + erow * 16 + ec0;
            int gn = n0 + wn * 32 + j * 16 + ec0;
            alignas(16) float v[8];
            #pragma unroll
            for (int t = 0; t < 8; ++t) {
                v[t] = sp[t] * alpha;
                if (bias) v[t] += bias[gn + t];
            }
            OutT* gp = C + (long long)(m0 + wm * 32 + i * 16 + erow) * ldc + gn;
            if (sizeof(OutT) == 2) {
                alignas(16) __half hv[8];
                #pragma unroll
                for (int t = 0; t < 8; ++t) hv[t] = __float2half_rn(v[t]);
                *(uint4*)gp = *(uint4*)hv;
            } else {
                *(float4*)gp = *(float4*)&v[0];
                *(float4*)((float*)gp + 4) = *(float4*)&v[4];
            }
            __syncwarp();
        }
    }
}

// ---------------- row softmax, fp32 in -> half out ---------------------------
__global__ void softmax_kernel(const float* __restrict__ S,
                               __half* __restrict__ P) {
    size_t r = blockIdx.x;
    const float* row = S + r * S_LEN;
    __half* prow = P + r * S_LEN;
    int tid = threadIdx.x;

    float vals[S_LEN / 256];
    float mx = -INFINITY;
    #pragma unroll
    for (int i = 0; i < S_LEN / 256; ++i) {
        vals[i] = row[tid + i * 256];
        mx = fmaxf(mx, vals[i]);
    }
    __shared__ float red[256];
    red[tid] = mx;
    __syncthreads();
    #pragma unroll
    for (int off = 128; off > 0; off >>= 1) {
        if (tid < off) red[tid] = fmaxf(red[tid], red[tid + off]);
        __syncthreads();
    }
    mx = red[0];
    __syncthreads();

    float sum = 0.f;
    #pragma unroll
    for (int i = 0; i < S_LEN / 256; ++i) {
        vals[i] = __expf(vals[i] - mx);
        sum += vals[i];
    }
    red[tid] = sum;
    __syncthreads();
    #pragma unroll
    for (int off = 128; off > 0; off >>= 1) {
        if (tid < off) red[tid] += red[tid + off];
        __syncthreads();
    }
    float inv = 1.0f / red[0];
    #pragma unroll
    for (int i = 0; i < S_LEN / 256; ++i)
        prow[tid + i * 256] = __float2half_rn(vals[i] * inv);
}

// ---------------- launch ------------------------------------------------------
extern "C" void kernel_launch(void* const* d_in, const int* in_sizes, int n_in,
                              void* d_out, int out_size) {
    const float* x   = (const float*)d_in[0];
    const float* fa  = (const float*)d_in[1];
    const float* Wq  = (const float*)d_in[2];
    const float* bq  = (const float*)d_in[3];
    const float* Wk  = (const float*)d_in[4];
    const float* bk  = (const float*)d_in[5];
    const float* Wv  = (const float*)d_in[6];
    const float* bv  = (const float*)d_in[7];
    const float* Wo  = (const float*)d_in[8];
    const float* bo  = (const float*)d_in[9];
    const float* gq  = (const float*)d_in[10];
    const float* gk  = (const float*)d_in[11];
    float* out = (float*)d_out;

    float *Qp, *Kp, *Vp, *Sp, *Cp, *Sn;
    __half *xh, *Wqh, *Wkh, *Wvh, *Woh, *Qh, *Kh, *Vth, *Ph, *Oh;
    cudaGetSymbolAddress((void**)&Qp, g_Q);
    cudaGetSymbolAddress((void**)&Kp, g_K);
    cudaGetSymbolAddress((void**)&Vp, g_V);
    cudaGetSymbolAddress((void**)&Sp, g_S);
    cudaGetSymbolAddress((void**)&Cp, g_cos);
    cudaGetSymbolAddress((void**)&Sn, g_sin);
    cudaGetSymbolAddress((void**)&xh, g_xh);
    cudaGetSymbolAddress((void**)&Wqh, g_Wqh);
    cudaGetSymbolAddress((void**)&Wkh, g_Wkh);
    cudaGetSymbolAddress((void**)&Wvh, g_Wvh);
    cudaGetSymbolAddress((void**)&Woh, g_Woh);
    cudaGetSymbolAddress((void**)&Qh, g_Qh);
    cudaGetSymbolAddress((void**)&Kh, g_Kh);
    cudaGetSymbolAddress((void**)&Vth, g_Vth);
    cudaGetSymbolAddress((void**)&Ph, g_Ph);
    cudaGetSymbolAddress((void**)&Oh, g_Oh);

    rope_table_kernel<<<(S_LEN * C_HALF + 255) / 256, 256>>>(fa, Cp, Sn);

    // convert inputs to half
    int nx4 = S_LEN * DIM_ / 4, nw4 = DIM_ * DIM_ / 4;
    f2h_kernel<<<(nx4 + 255) / 256, 256>>>(x, xh, nx4);
    f2h_kernel<<<(nw4 + 255) / 256, 256>>>(Wq, Wqh, nw4);
    f2h_kernel<<<(nw4 + 255) / 256, 256>>>(Wk, Wkh, nw4);
    f2h_kernel<<<(nw4 + 255) / 256, 256>>>(Wv, Wvh, nw4);
    f2h_kernel<<<(nw4 + 255) / 256, 256>>>(Wo, Woh, nw4);

    // QKV projections (half in, fp32 out)
    dim3 gProj(DIM_ / 128, S_LEN / 128, 1);
    gemm_nt_h<float><<<gProj, 512>>>(xh, Wqh, Qp, bq, DIM_, DIM_, DIM_, DIM_,
                                     0, 0, 0, 1.0f);
    gemm_nt_h<float><<<gProj, 512>>>(xh, Wkh, Kp, bk, DIM_, DIM_, DIM_, DIM_,
                                     0, 0, 0, 1.0f);
    gemm_nt_h<float><<<gProj, 512>>>(xh, Wvh, Vp, bv, DIM_, DIM_, DIM_, DIM_,
                                     0, 0, 0, 1.0f);

    // RMSNorm + RoPE -> half Q/K
    rms_rope_kernel<<<S_LEN, 256>>>(Qp, Qh, gq, Cp, Sn);
    rms_rope_kernel<<<S_LEN, 256>>>(Kp, Kh, gk, Cp, Sn);

    // V transpose -> half Vt
    transpose_kernel<<<dim3(DIM_ / 32, S_LEN / 32), dim3(32, 8)>>>(Vp, Vth);

    // scores[h] = scale * Q_h @ K_h^T (fp32 out)
    const float scale = 0.08838834764831845f;
    dim3 gScore(S_LEN / 128, S_LEN / 128, NH);
    gemm_nt_h<float><<<gScore, 512>>>(Qh, Kh, Sp, nullptr, HD, DIM_, DIM_,
                                      S_LEN, (long long)HD, (long long)HD,
                                      (long long)S_LEN * S_LEN, scale);

    // softmax -> half P
    softmax_kernel<<<NH * S_LEN, 256>>>(Sp, Ph);

    // O[h] = P_h @ Vt_h^T  -> half O
    dim3 gPV(HD / 128, S_LEN / 128, NH);
    gemm_nt_h<__half><<<gPV, 512>>>(Ph, Vth, Oh, nullptr, S_LEN, S_LEN, S_LEN,
                                    DIM_, (long long)S_LEN * S_LEN,
                                    (long long)HD * S_LEN, (long long)HD, 1.0f);

    // out = O @ Wo^T + bo (fp32)
    gemm_nt_h<float><<<gProj, 512>>>(Oh, Woh, out, bo, DIM_, DIM_, DIM_, DIM_,
                                     0, 0, 0, 1.0f);
}

// round 5
// speedup vs baseline: 6.1549x; 1.5296x over previous
#include <cuda_runtime.h>
#include <cuda_fp16.h>
#include <mma.h>
#include <math.h>

using namespace nvcuda;

#define S_LEN  3072
#define DIM_   2048
#define NH     16
#define HD     128
#define C_HALF 64
#define GF 8
#define GH 16
#define GW 24
#define CF 22
#define CH 21
#define LDH 40    // GEMM half-tile leading dim (32 + 8 pad)
#define LDK 136   // flash smem leading dim (128 + 8 pad, keeps 16B align)

// ---------------- scratch ----------------------------------------------------
__device__ float  g_Q[(size_t)S_LEN * DIM_];
__device__ float  g_K[(size_t)S_LEN * DIM_];
__device__ __half g_xh[(size_t)S_LEN * DIM_];
__device__ __half g_Wqh[(size_t)DIM_ * DIM_];
__device__ __half g_Wkh[(size_t)DIM_ * DIM_];
__device__ __half g_Wvh[(size_t)DIM_ * DIM_];
__device__ __half g_Woh[(size_t)DIM_ * DIM_];
__device__ __half g_Qh[(size_t)S_LEN * DIM_];
__device__ __half g_Kh[(size_t)S_LEN * DIM_];
__device__ __half g_Vh[(size_t)S_LEN * DIM_];
__device__ __half g_Oh[(size_t)S_LEN * DIM_];
__device__ float  g_cos[S_LEN * C_HALF];
__device__ float  g_sin[S_LEN * C_HALF];

// ---------------- float -> half convert --------------------------------------
__global__ void f2h_kernel(const float* __restrict__ in,
                           __half* __restrict__ out, int n4) {
    int i = blockIdx.x * blockDim.x + threadIdx.x;
    if (i >= n4) return;
    float4 v = ((const float4*)in)[i];
    ((half2*)out)[2 * i]     = __floats2half2_rn(v.x, v.y);
    ((half2*)out)[2 * i + 1] = __floats2half2_rn(v.z, v.w);
}

// ---------------- RoPE angle table ------------------------------------------
__global__ void rope_table_kernel(const float* __restrict__ fa,
                                  float* __restrict__ ctab,
                                  float* __restrict__ stab) {
    int idx = blockIdx.x * blockDim.x + threadIdx.x;
    if (idx >= S_LEN * C_HALF) return;
    int s = idx >> 6;
    int j = idx & 63;
    int f = s / (GH * GW);
    int h = (s / GW) % GH;
    int w = s % GW;
    int row = (j < CF) ? f : (j < CF + CH) ? h : w;
    float a = fa[row * C_HALF + j];
    ctab[idx] = cosf(a);
    stab[idx] = sinf(a);
}

// ---------------- fused RMSNorm + RoPE, fp32 in -> half out (scaled) ---------
__global__ void rms_rope_kernel(const float* __restrict__ in,
                                __half* __restrict__ out,
                                const float* __restrict__ g,
                                const float* __restrict__ ctab,
                                const float* __restrict__ stab,
                                float scale) {
    int s = blockIdx.x;
    const float* row = in + (size_t)s * DIM_;
    half2* orow = (half2*)(out + (size_t)s * DIM_);
    int tid = threadIdx.x;

    float ss = 0.f;
    #pragma unroll
    for (int i = tid; i < DIM_; i += 256) {
        float v = row[i];
        ss += v * v;
    }
    __shared__ float red[256];
    red[tid] = ss;
    __syncthreads();
    #pragma unroll
    for (int off = 128; off > 0; off >>= 1) {
        if (tid < off) red[tid] += red[tid + off];
        __syncthreads();
    }
    float inv = rsqrtf(red[0] * (1.0f / DIM_) + 1e-6f) * scale;

    const float* crow = ctab + s * C_HALF;
    const float* srow = stab + s * C_HALF;
    #pragma unroll
    for (int p = tid; p < DIM_ / 2; p += 256) {
        int j = p & (C_HALF - 1);
        float c = crow[j], sn = srow[j];
        float te = row[2 * p]     * inv * g[2 * p];
        float to = row[2 * p + 1] * inv * g[2 * p + 1];
        orow[p] = __floats2half2_rn(te * c - to * sn, te * sn + to * c);
    }
}

// ---------------- cp.async helpers -------------------------------------------
__device__ __forceinline__ void cp_async16(void* smem, const void* gmem) {
    unsigned s = (unsigned)__cvta_generic_to_shared(smem);
    asm volatile("cp.async.cg.shared.global [%0], [%1], 16;\n"
                 :: "r"(s), "l"(gmem));
}
__device__ __forceinline__ void cp_commit() {
    asm volatile("cp.async.commit_group;\n");
}
template <int N>
__device__ __forceinline__ void cp_wait() {
    asm volatile("cp.async.wait_group %0;\n" :: "n"(N));
}

// ---------------- mma / ldmatrix helpers -------------------------------------
__device__ __forceinline__ void mma16816(float* c, const unsigned* a,
                                         const unsigned* b) {
    asm volatile("mma.sync.aligned.m16n8k16.row.col.f32.f16.f16.f32 "
                 "{%0,%1,%2,%3}, {%4,%5,%6,%7}, {%8,%9}, {%0,%1,%2,%3};\n"
                 : "+f"(c[0]), "+f"(c[1]), "+f"(c[2]), "+f"(c[3])
                 : "r"(a[0]), "r"(a[1]), "r"(a[2]), "r"(a[3]),
                   "r"(b[0]), "r"(b[1]));
}
__device__ __forceinline__ void ldsm_x4(unsigned* r, unsigned a) {
    asm volatile("ldmatrix.sync.aligned.m8n8.x4.shared.b16 {%0,%1,%2,%3}, [%4];\n"
                 : "=r"(r[0]), "=r"(r[1]), "=r"(r[2]), "=r"(r[3]) : "r"(a));
}
__device__ __forceinline__ void ldsm_x2(unsigned* r, unsigned a) {
    asm volatile("ldmatrix.sync.aligned.m8n8.x2.shared.b16 {%0,%1}, [%2];\n"
                 : "=r"(r[0]), "=r"(r[1]) : "r"(a));
}
__device__ __forceinline__ void ldsm_x2t(unsigned* r, unsigned a) {
    asm volatile("ldmatrix.sync.aligned.m8n8.x2.trans.shared.b16 {%0,%1}, [%2];\n"
                 : "=r"(r[0]), "=r"(r[1]) : "r"(a));
}
__device__ __forceinline__ unsigned packh2(float a, float b) {
    half2 h = __floats2half2_rn(a, b);
    return *(unsigned*)&h;
}

// ---------------- flash attention kernel -------------------------------------
// grid (S_LEN/128, NH), 256 threads (8 warps). Q tile 128x128 in regs,
// K/V streamed in 64-key chunks, online softmax in registers, O in regs.
#define FLASH_SMEM (4 * 64 * LDK * 2)   // K(2 stages) + V(2 stages), halves*2B

__global__ __launch_bounds__(256, 1)
void flash_kernel(const __half* __restrict__ Q, const __half* __restrict__ K,
                  const __half* __restrict__ V, __half* __restrict__ O) {
    extern __shared__ __half sm[];
    __half* sK = sm;                    // [2][64][LDK]
    __half* sV = sm + 2 * 64 * LDK;     // [2][64][LDK]

    int q0 = blockIdx.x * 128;
    int h  = blockIdx.y;
    int tid = threadIdx.x;
    int w = tid >> 5, lane = tid & 31;
    int g = lane >> 2, qp = lane & 3;
    int wm0 = w * 16;

    const __half* Qg = Q + (size_t)q0 * DIM_ + h * HD;
    const __half* Kg = K + h * HD;
    const __half* Vg = V + h * HD;

    // ---- stage Q (128x128) into sK region, extract A fragments ----
    #pragma unroll
    for (int it = 0; it < 8; ++it) {
        int slot = tid + it * 256;
        int r = slot >> 4, c = (slot & 15) << 3;
        cp_async16(&sK[r * LDK + c], Qg + (size_t)r * DIM_ + c);
    }
    cp_commit();
    cp_wait<0>();
    __syncthreads();

    unsigned qf[8][4];
    {
        unsigned base = (unsigned)__cvta_generic_to_shared(sK);
        int row = wm0 + (lane & 7) + (lane & 8);
        #pragma unroll
        for (int kk = 0; kk < 8; ++kk) {
            int col = kk * 16 + ((lane & 16) >> 1);
            ldsm_x4(qf[kk], base + (row * LDK + col) * 2);
        }
    }
    __syncthreads();

    float oacc[16][4];
    #pragma unroll
    for (int t = 0; t < 16; ++t)
        #pragma unroll
        for (int c = 0; c < 4; ++c) oacc[t][c] = 0.f;
    float mA = -1e30f, mB = -1e30f, lA = 0.f, lB = 0.f;

    // prologue: load chunk 0 into stage 0
    #pragma unroll
    for (int it = 0; it < 4; ++it) {
        int slot = tid + it * 256;
        int r = slot >> 4, c = (slot & 15) << 3;
        cp_async16(&sK[r * LDK + c], Kg + (size_t)r * DIM_ + c);
        cp_async16(&sV[r * LDK + c], Vg + (size_t)r * DIM_ + c);
    }
    cp_commit();

    const int NCH = S_LEN / 64;
    for (int i = 0; i < NCH; ++i) {
        cp_wait<0>();
        __syncthreads();

        if (i + 1 < NCH) {
            int st = (i + 1) & 1;
            const __half* kg = Kg + (size_t)(i + 1) * 64 * DIM_;
            const __half* vg = Vg + (size_t)(i + 1) * 64 * DIM_;
            __half* dK = sK + st * 64 * LDK;
            __half* dV = sV + st * 64 * LDK;
            #pragma unroll
            for (int it = 0; it < 4; ++it) {
                int slot = tid + it * 256;
                int r = slot >> 4, c = (slot & 15) << 3;
                cp_async16(&dK[r * LDK + c], kg + (size_t)r * DIM_ + c);
                cp_async16(&dV[r * LDK + c], vg + (size_t)r * DIM_ + c);
            }
            cp_commit();
        }

        int st = i & 1;
        unsigned kbase = (unsigned)__cvta_generic_to_shared(sK + st * 64 * LDK);
        unsigned vbase = (unsigned)__cvta_generic_to_shared(sV + st * 64 * LDK);

        // S = Q @ K_chunk^T : warp computes 16 x 64
        float sacc[8][4];
        #pragma unroll
        for (int j = 0; j < 8; ++j) {
            sacc[j][0] = sacc[j][1] = sacc[j][2] = sacc[j][3] = 0.f;
        }
        #pragma unroll
        for (int j = 0; j < 8; ++j) {
            int krow = 8 * j + (lane & 7);
            #pragma unroll
            for (int kk = 0; kk < 8; ++kk) {
                unsigned b[2];
                int kcol = 16 * kk + (lane & 8);
                ldsm_x2(b, kbase + (krow * LDK + kcol) * 2);
                mma16816(sacc[j], qf[kk], b);
            }
        }

        // online softmax (rows g and g+8 of this warp's 16)
        float cmA = -1e30f, cmB = -1e30f;
        #pragma unroll
        for (int j = 0; j < 8; ++j) {
            cmA = fmaxf(cmA, fmaxf(sacc[j][0], sacc[j][1]));
            cmB = fmaxf(cmB, fmaxf(sacc[j][2], sacc[j][3]));
        }
        cmA = fmaxf(cmA, __shfl_xor_sync(0xffffffffu, cmA, 1));
        cmA = fmaxf(cmA, __shfl_xor_sync(0xffffffffu, cmA, 2));
        cmB = fmaxf(cmB, __shfl_xor_sync(0xffffffffu, cmB, 1));
        cmB = fmaxf(cmB, __shfl_xor_sync(0xffffffffu, cmB, 2));
        float mAn = fmaxf(mA, cmA), mBn = fmaxf(mB, cmB);
        float fA = __expf(mA - mAn), fB = __expf(mB - mBn);

        float sumA = 0.f, sumB = 0.f;
        #pragma unroll
        for (int j = 0; j < 8; ++j) {
            sacc[j][0] = __expf(sacc[j][0] - mAn);
            sacc[j][1] = __expf(sacc[j][1] - mAn);
            sacc[j][2] = __expf(sacc[j][2] - mBn);
            sacc[j][3] = __expf(sacc[j][3] - mBn);
            sumA += sacc[j][0] + sacc[j][1];
            sumB += sacc[j][2] + sacc[j][3];
        }
        sumA += __shfl_xor_sync(0xffffffffu, sumA, 1);
        sumA += __shfl_xor_sync(0xffffffffu, sumA, 2);
        sumB += __shfl_xor_sync(0xffffffffu, sumB, 1);
        sumB += __shfl_xor_sync(0xffffffffu, sumB, 2);
        lA = lA * fA + sumA;
        lB = lB * fB + sumB;
        mA = mAn; mB = mBn;

        #pragma unroll
        for (int t = 0; t < 16; ++t) {
            oacc[t][0] *= fA; oacc[t][1] *= fA;
            oacc[t][2] *= fB; oacc[t][3] *= fB;
        }

        // re-pack S-accumulator fragments as P A-fragments
        unsigned pf[4][4];
        #pragma unroll
        for (int kt = 0; kt < 4; ++kt) {
            pf[kt][0] = packh2(sacc[2 * kt][0],     sacc[2 * kt][1]);
            pf[kt][1] = packh2(sacc[2 * kt][2],     sacc[2 * kt][3]);
            pf[kt][2] = packh2(sacc[2 * kt + 1][0], sacc[2 * kt + 1][1]);
            pf[kt][3] = packh2(sacc[2 * kt + 1][2], sacc[2 * kt + 1][3]);
        }

        // O += P @ V_chunk
        #pragma unroll
        for (int t = 0; t < 16; ++t) {
            #pragma unroll
            for (int kt = 0; kt < 4; ++kt) {
                unsigned b[2];
                int vrow = 16 * kt + (lane & 15);
                ldsm_x2t(b, vbase + (vrow * LDK + 8 * t) * 2);
                mma16816(oacc[t], pf[kt], b);
            }
        }
    }

    // epilogue: normalize by l, write half
    float invA = 1.f / lA, invB = 1.f / lB;
    size_t b0 = (size_t)(q0 + wm0 + g) * DIM_ + h * HD + qp * 2;
    size_t b1 = b0 + (size_t)8 * DIM_;
    #pragma unroll
    for (int t = 0; t < 16; ++t) {
        *(half2*)&O[b0 + 8 * t] =
            __floats2half2_rn(oacc[t][0] * invA, oacc[t][1] * invA);
        *(half2*)&O[b1 + 8 * t] =
            __floats2half2_rn(oacc[t][2] * invB, oacc[t][3] * invB);
    }
}

// ---------------- fp16 tensor-core GEMM NT, cp.async double-buffered ---------
template <typename OutT>
__global__ __launch_bounds__(512, 1)
void gemm_nt_h(const __half* __restrict__ A, const __half* __restrict__ B,
               OutT* __restrict__ C, const float* __restrict__ bias,
               int K, int lda, int ldb, int ldc,
               long long sA, long long sB, long long sC, float alpha) {
    __shared__ __half sh[2][2][128 * LDH];

    A += (long long)blockIdx.z * sA;
    B += (long long)blockIdx.z * sB;
    C += (long long)blockIdx.z * sC;
    int m0 = blockIdx.y * 128, n0 = blockIdx.x * 128;
    int tid = threadIdx.x;
    int w = tid >> 5, lane = tid & 31;
    int wm = w & 3, wn = w >> 2;

    int lrow = tid >> 2, lch = (tid & 3) << 3;
    const __half* gA = A + (long long)(m0 + lrow) * lda + lch;
    const __half* gB = B + (long long)(n0 + lrow) * ldb + lch;
    __half* sAslot0 = &sh[0][0][lrow * LDH + lch];
    __half* sBslot0 = &sh[0][1][lrow * LDH + lch];
    __half* sAslot1 = &sh[1][0][lrow * LDH + lch];
    __half* sBslot1 = &sh[1][1][lrow * LDH + lch];

    wmma::fragment<wmma::accumulator, 16, 16, 16, float> cf[2][2];
    #pragma unroll
    for (int i = 0; i < 2; ++i)
        #pragma unroll
        for (int j = 0; j < 2; ++j) wmma::fill_fragment(cf[i][j], 0.f);

    int nk = K >> 5;
    cp_async16(sAslot0, gA);
    cp_async16(sBslot0, gB);
    cp_commit();

    for (int it = 0; it < nk; ++it) {
        if (it + 1 < nk) {
            int koff = (it + 1) << 5;
            if ((it + 1) & 1) {
                cp_async16(sAslot1, gA + koff);
                cp_async16(sBslot1, gB + koff);
            } else {
                cp_async16(sAslot0, gA + koff);
                cp_async16(sBslot0, gB + koff);
            }
            cp_commit();
            cp_wait<1>();
        } else {
            cp_wait<0>();
        }
        __syncthreads();

        const __half* As = sh[it & 1][0];
        const __half* Bs = sh[it & 1][1];
        #pragma unroll
        for (int kk = 0; kk < 32; kk += 16) {
            wmma::fragment<wmma::matrix_a, 16, 16, 16, __half,
                           wmma::row_major> af[2];
            wmma::fragment<wmma::matrix_b, 16, 16, 16, __half,
                           wmma::col_major> bf[2];
            #pragma unroll
            for (int i = 0; i < 2; ++i)
                wmma::load_matrix_sync(af[i],
                    &As[(wm * 32 + i * 16) * LDH + kk], LDH);
            #pragma unroll
            for (int j = 0; j < 2; ++j)
                wmma::load_matrix_sync(bf[j],
                    &Bs[(wn * 32 + j * 16) * LDH + kk], LDH);
            #pragma unroll
            for (int i = 0; i < 2; ++i)
                #pragma unroll
                for (int j = 0; j < 2; ++j)
                    wmma::mma_sync(cf[i][j], af[i], bf[j], cf[i][j]);
        }
        __syncthreads();
    }

    float* stage = reinterpret_cast<float*>(&sh[0][0][0]) + w * 256;
    int erow = lane >> 1, ec0 = (lane & 1) << 3;
    #pragma unroll
    for (int i = 0; i < 2; ++i) {
        #pragma unroll
        for (int j = 0; j < 2; ++j) {
            wmma::store_matrix_sync(stage, cf[i][j], 16, wmma::mem_row_major);
            __syncwarp();
            const float* sp = stage + erow * 16 + ec0;
            int gn = n0 + wn * 32 + j * 16 + ec0;
            alignas(16) float v[8];
            #pragma unroll
            for (int t = 0; t < 8; ++t) {
                v[t] = sp[t] * alpha;
                if (bias) v[t] += bias[gn + t];
            }
            OutT* gp = C + (long long)(m0 + wm * 32 + i * 16 + erow) * ldc + gn;
            if (sizeof(OutT) == 2) {
                alignas(16) __half hv[8];
                #pragma unroll
                for (int t = 0; t < 8; ++t) hv[t] = __float2half_rn(v[t]);
                *(uint4*)gp = *(uint4*)hv;
            } else {
                *(float4*)gp = *(float4*)&v[0];
                *(float4*)((float*)gp + 4) = *(float4*)&v[4];
            }
            __syncwarp();
        }
    }
}

// ---------------- launch ------------------------------------------------------
extern "C" void kernel_launch(void* const* d_in, const int* in_sizes, int n_in,
                              void* d_out, int out_size) {
    const float* x   = (const float*)d_in[0];
    const float* fa  = (const float*)d_in[1];
    const float* Wq  = (const float*)d_in[2];
    const float* bq  = (const float*)d_in[3];
    const float* Wk  = (const float*)d_in[4];
    const float* bk  = (const float*)d_in[5];
    const float* Wv  = (const float*)d_in[6];
    const float* bv  = (const float*)d_in[7];
    const float* Wo  = (const float*)d_in[8];
    const float* bo  = (const float*)d_in[9];
    const float* gq  = (const float*)d_in[10];
    const float* gk  = (const float*)d_in[11];
    float* out = (float*)d_out;

    float *Qp, *Kp, *Cp, *Sn;
    __half *xh, *Wqh, *Wkh, *Wvh, *Woh, *Qh, *Kh, *Vh, *Oh;
    cudaGetSymbolAddress((void**)&Qp, g_Q);
    cudaGetSymbolAddress((void**)&Kp, g_K);
    cudaGetSymbolAddress((void**)&Cp, g_cos);
    cudaGetSymbolAddress((void**)&Sn, g_sin);
    cudaGetSymbolAddress((void**)&xh, g_xh);
    cudaGetSymbolAddress((void**)&Wqh, g_Wqh);
    cudaGetSymbolAddress((void**)&Wkh, g_Wkh);
    cudaGetSymbolAddress((void**)&Wvh, g_Wvh);
    cudaGetSymbolAddress((void**)&Woh, g_Woh);
    cudaGetSymbolAddress((void**)&Qh, g_Qh);
    cudaGetSymbolAddress((void**)&Kh, g_Kh);
    cudaGetSymbolAddress((void**)&Vh, g_Vh);
    cudaGetSymbolAddress((void**)&Oh, g_Oh);

    cudaFuncSetAttribute(flash_kernel,
                         cudaFuncAttributeMaxDynamicSharedMemorySize,
                         FLASH_SMEM);

    rope_table_kernel<<<(S_LEN * C_HALF + 255) / 256, 256>>>(fa, Cp, Sn);

    int nx4 = S_LEN * DIM_ / 4, nw4 = DIM_ * DIM_ / 4;
    f2h_kernel<<<(nx4 + 255) / 256, 256>>>(x, xh, nx4);
    f2h_kernel<<<(nw4 + 255) / 256, 256>>>(Wq, Wqh, nw4);
    f2h_kernel<<<(nw4 + 255) / 256, 256>>>(Wk, Wkh, nw4);
    f2h_kernel<<<(nw4 + 255) / 256, 256>>>(Wv, Wvh, nw4);
    f2h_kernel<<<(nw4 + 255) / 256, 256>>>(Wo, Woh, nw4);

    // QKV projections (V straight to half)
    dim3 gProj(DIM_ / 128, S_LEN / 128, 1);
    gemm_nt_h<float><<<gProj, 512>>>(xh, Wqh, Qp, bq, DIM_, DIM_, DIM_, DIM_,
                                     0, 0, 0, 1.0f);
    gemm_nt_h<float><<<gProj, 512>>>(xh, Wkh, Kp, bk, DIM_, DIM_, DIM_, DIM_,
                                     0, 0, 0, 1.0f);
    gemm_nt_h<__half><<<gProj, 512>>>(xh, Wvh, Vh, bv, DIM_, DIM_, DIM_, DIM_,
                                      0, 0, 0, 1.0f);

    // RMSNorm + RoPE -> half Q (pre-scaled by 1/sqrt(d)) and K
    rms_rope_kernel<<<S_LEN, 256>>>(Qp, Qh, gq, Cp, Sn, 0.08838834764831845f);
    rms_rope_kernel<<<S_LEN, 256>>>(Kp, Kh, gk, Cp, Sn, 1.0f);

    // fused attention
    dim3 gFlash(S_LEN / 128, NH);
    flash_kernel<<<gFlash, 256, FLASH_SMEM>>>(Qh, Kh, Vh, Oh);

    // out = O @ Wo^T + bo (fp32)
    gemm_nt_h<float><<<gProj, 512>>>(Oh, Woh, out, bo, DIM_, DIM_, DIM_, DIM_,
                                     0, 0, 0, 1.0f);
}

// round 8
// speedup vs baseline: 7.9594x; 1.2932x over previous
#include <cuda_runtime.h>
#include <cuda_fp16.h>
#include <math.h>
#include <stdint.h>

#define S_LEN  3072
#define DIM_   2048
#define NH     16
#define HD     128
#define C_HALF 64
#define GF 8
#define GH 16
#define GW 24
#define CF 22
#define CH 21
#define LDK 136   // flash smem leading dim (128 + 8 pad)

// ---------------- scratch ----------------------------------------------------
__device__ float  g_Q[(size_t)S_LEN * DIM_];
__device__ float  g_K[(size_t)S_LEN * DIM_];
__device__ __half g_xh[(size_t)S_LEN * DIM_];
__device__ __half g_Wqh[(size_t)DIM_ * DIM_];
__device__ __half g_Wkh[(size_t)DIM_ * DIM_];
__device__ __half g_Wvh[(size_t)DIM_ * DIM_];
__device__ __half g_Woh[(size_t)DIM_ * DIM_];
__device__ __half g_Qh[(size_t)S_LEN * DIM_];
__device__ __half g_Kh[(size_t)S_LEN * DIM_];
__device__ __half g_Vh[(size_t)S_LEN * DIM_];
__device__ __half g_Oh[(size_t)S_LEN * DIM_];
__device__ float  g_cos[S_LEN * C_HALF];
__device__ float  g_sin[S_LEN * C_HALF];

// ---------------- small kernels ----------------------------------------------
__global__ void f2h_kernel(const float* __restrict__ in,
                           __half* __restrict__ out, int n4) {
    int i = blockIdx.x * blockDim.x + threadIdx.x;
    if (i >= n4) return;
    float4 v = ((const float4*)in)[i];
    ((half2*)out)[2 * i]     = __floats2half2_rn(v.x, v.y);
    ((half2*)out)[2 * i + 1] = __floats2half2_rn(v.z, v.w);
}

// 4 weight matrices in one launch (grid.y selects)
__global__ void w4h_kernel(const float* __restrict__ W0, const float* __restrict__ W1,
                           const float* __restrict__ W2, const float* __restrict__ W3,
                           __half* __restrict__ O0, __half* __restrict__ O1,
                           __half* __restrict__ O2, __half* __restrict__ O3, int n4) {
    int i = blockIdx.x * blockDim.x + threadIdx.x;
    if (i >= n4) return;
    int z = blockIdx.y;
    const float* in = (z == 0) ? W0 : (z == 1) ? W1 : (z == 2) ? W2 : W3;
    __half* out = (z == 0) ? O0 : (z == 1) ? O1 : (z == 2) ? O2 : O3;
    float4 v = ((const float4*)in)[i];
    ((half2*)out)[2 * i]     = __floats2half2_rn(v.x, v.y);
    ((half2*)out)[2 * i + 1] = __floats2half2_rn(v.z, v.w);
}

__global__ void rope_table_kernel(const float* __restrict__ fa,
                                  float* __restrict__ ctab,
                                  float* __restrict__ stab) {
    int idx = blockIdx.x * blockDim.x + threadIdx.x;
    if (idx >= S_LEN * C_HALF) return;
    int s = idx >> 6;
    int j = idx & 63;
    int f = s / (GH * GW);
    int h = (s / GW) % GH;
    int w = s % GW;
    int row = (j < CF) ? f : (j < CF + CH) ? h : w;
    float a = fa[row * C_HALF + j];
    ctab[idx] = cosf(a);
    stab[idx] = sinf(a);
}

__global__ void rms_rope_kernel(const float* __restrict__ in,
                                __half* __restrict__ out,
                                const float* __restrict__ g,
                                const float* __restrict__ ctab,
                                const float* __restrict__ stab,
                                float scale) {
    int s = blockIdx.x;
    const float* row = in + (size_t)s * DIM_;
    half2* orow = (half2*)(out + (size_t)s * DIM_);
    int tid = threadIdx.x;

    float ss = 0.f;
    #pragma unroll
    for (int i = tid; i < DIM_; i += 256) {
        float v = row[i];
        ss += v * v;
    }
    __shared__ float red[256];
    red[tid] = ss;
    __syncthreads();
    #pragma unroll
    for (int off = 128; off > 0; off >>= 1) {
        if (tid < off) red[tid] += red[tid + off];
        __syncthreads();
    }
    float inv = rsqrtf(red[0] * (1.0f / DIM_) + 1e-6f) * scale;

    const float* crow = ctab + s * C_HALF;
    const float* srow = stab + s * C_HALF;
    #pragma unroll
    for (int p = tid; p < DIM_ / 2; p += 256) {
        int j = p & (C_HALF - 1);
        float c = crow[j], sn = srow[j];
        float te = row[2 * p]     * inv * g[2 * p];
        float to = row[2 * p + 1] * inv * g[2 * p + 1];
        orow[p] = __floats2half2_rn(te * c - to * sn, te * sn + to * c);
    }
}

// ---------------- cp.async / mma helpers -------------------------------------
__device__ __forceinline__ void cp_async16(void* smem, const void* gmem) {
    unsigned s = (unsigned)__cvta_generic_to_shared(smem);
    asm volatile("cp.async.cg.shared.global [%0], [%1], 16;\n"
                 :: "r"(s), "l"(gmem));
}
__device__ __forceinline__ void cp_commit() {
    asm volatile("cp.async.commit_group;\n");
}
template <int N>
__device__ __forceinline__ void cp_wait() {
    asm volatile("cp.async.wait_group %0;\n" :: "n"(N));
}

__device__ __forceinline__ void mma16816(float* c, const unsigned* a,
                                         const unsigned* b) {
    asm volatile("mma.sync.aligned.m16n8k16.row.col.f32.f16.f16.f32 "
                 "{%0,%1,%2,%3}, {%4,%5,%6,%7}, {%8,%9}, {%0,%1,%2,%3};\n"
                 : "+f"(c[0]), "+f"(c[1]), "+f"(c[2]), "+f"(c[3])
                 : "r"(a[0]), "r"(a[1]), "r"(a[2]), "r"(a[3]),
                   "r"(b[0]), "r"(b[1]));
}
__device__ __forceinline__ void ldsm_x4(unsigned* r, unsigned a) {
    asm volatile("ldmatrix.sync.aligned.m8n8.x4.shared.b16 {%0,%1,%2,%3}, [%4];\n"
                 : "=r"(r[0]), "=r"(r[1]), "=r"(r[2]), "=r"(r[3]) : "r"(a));
}
__device__ __forceinline__ void ldsm_x2(unsigned* r, unsigned a) {
    asm volatile("ldmatrix.sync.aligned.m8n8.x2.shared.b16 {%0,%1}, [%2];\n"
                 : "=r"(r[0]), "=r"(r[1]) : "r"(a));
}
__device__ __forceinline__ void ldsm_x2t(unsigned* r, unsigned a) {
    asm volatile("ldmatrix.sync.aligned.m8n8.x2.trans.shared.b16 {%0,%1}, [%2];\n"
                 : "=r"(r[0]), "=r"(r[1]) : "r"(a));
}
__device__ __forceinline__ unsigned packh2(float a, float b) {
    half2 h = __floats2half2_rn(a, b);
    return *(unsigned*)&h;
}

// ---------------- mma.sync GEMM NT: C = A(3072x2048) @ B(2048x2048)^T + bias -
// block 128x128, 8 warps (4m x 2n), warp tile 32x64, k-step 32, 3-stage pipe.
// grid.z selects (B, bias, C): z=0,1 -> fp32 out, z=2 -> half out.
#define GSTG 3
#define GLD 40                        // smem leading dim (32 + 8 pad halfs)
#define GSLOT (2 * 128 * GLD)         // halfs per stage (A then B)
#define GEMM_SMEM (GSTG * GSLOT * 2)  // bytes = 61440

__global__ __launch_bounds__(256, 2)
void gemm_mma(const __half* __restrict__ A,
              const __half* __restrict__ B0, const __half* __restrict__ B1,
              const __half* __restrict__ B2,
              const float* __restrict__ bias0, const float* __restrict__ bias1,
              const float* __restrict__ bias2,
              float* __restrict__ Cf0, float* __restrict__ Cf1,
              __half* __restrict__ Ch2) {
    extern __shared__ __half gsm[];
    int z = blockIdx.z;
    const __half* Bw = (z == 0) ? B0 : (z == 1) ? B1 : B2;
    const float* bias = (z == 0) ? bias0 : (z == 1) ? bias1 : bias2;

    int m0 = blockIdx.y * 128, n0 = blockIdx.x * 128;
    int tid = threadIdx.x;
    int w = tid >> 5, lane = tid & 31;
    int wm = w & 3, wn = w >> 2;

    // loader mapping: 2 chunks per matrix per thread (rows lr, lr+64)
    int lr = tid >> 2, lc = (tid & 3) << 3;
    const __half* gA = A + (size_t)(m0 + lr) * DIM_ + lc;
    const __half* gB = Bw + (size_t)(n0 + lr) * DIM_ + lc;
    unsigned sbase = (unsigned)__cvta_generic_to_shared(gsm);

    // per-lane ldsm smem offsets (bytes), precomputed
    int a_r = (lane & 7) + (lane & 8);
    int a_c = (lane & 16) >> 1;
    int b_r = (lane & 7) + (((lane >> 4) & 1) << 3);
    int b_c = ((lane >> 3) & 1) << 3;

    float cacc[2][8][4];
    #pragma unroll
    for (int i = 0; i < 2; ++i)
        #pragma unroll
        for (int f = 0; f < 8; ++f)
            cacc[i][f][0] = cacc[i][f][1] = cacc[i][f][2] = cacc[i][f][3] = 0.f;

    const int nk = DIM_ / 32;   // 64

    // prologue: stages 0,1
    #pragma unroll
    for (int c = 0; c < 2; ++c) {
        __half* sA = gsm + c * GSLOT;
        __half* sB = sA + 128 * GLD;
        int kofs = c * 32;
        cp_async16(sA + lr * GLD + lc, gA + kofs);
        cp_async16(sA + (lr + 64) * GLD + lc, gA + kofs + (size_t)64 * DIM_);
        cp_async16(sB + lr * GLD + lc, gB + kofs);
        cp_async16(sB + (lr + 64) * GLD + lc, gB + kofs + (size_t)64 * DIM_);
        cp_commit();
    }

    for (int it = 0; it < nk; ++it) {
        if (it + 1 < nk) cp_wait<1>(); else cp_wait<0>();
        __syncthreads();

        // prefetch stage it+2 into slot (it+2)%3 (== (it-1)%3, safe post-barrier)
        if (it + 2 < nk) {
            int sl = (it + 2) % GSTG;
            __half* sA = gsm + sl * GSLOT;
            __half* sB = sA + 128 * GLD;
            int kofs = (it + 2) * 32;
            cp_async16(sA + lr * GLD + lc, gA + kofs);
            cp_async16(sA + (lr + 64) * GLD + lc, gA + kofs + (size_t)64 * DIM_);
            cp_async16(sB + lr * GLD + lc, gB + kofs);
            cp_async16(sB + (lr + 64) * GLD + lc, gB + kofs + (size_t)64 * DIM_);
            cp_commit();
        }

        // compute stage it
        unsigned abase = sbase + (unsigned)((it % GSTG) * GSLOT) * 2;
        unsigned bbase = abase + 128 * GLD * 2;
        #pragma unroll
        for (int kb = 0; kb < 32; kb += 16) {
            unsigned af[2][4];
            #pragma unroll
            for (int i = 0; i < 2; ++i)
                ldsm_x4(af[i], abase +
                    (unsigned)(((wm * 32 + i * 16 + a_r) * GLD) + kb + a_c) * 2);
            #pragma unroll
            for (int jj = 0; jj < 4; ++jj) {
                unsigned bf[4];
                ldsm_x4(bf, bbase +
                    (unsigned)(((wn * 64 + jj * 16 + b_r) * GLD) + kb + b_c) * 2);
                #pragma unroll
                for (int i = 0; i < 2; ++i) {
                    mma16816(cacc[i][jj * 2],     af[i], &bf[0]);
                    mma16816(cacc[i][jj * 2 + 1], af[i], &bf[2]);
                }
            }
        }
        __syncthreads();
    }

    // epilogue: direct writes, c-frag rows g/g+8, cols 2qp
    int g = lane >> 2, qp = lane & 3;
    #pragma unroll
    for (int i = 0; i < 2; ++i) {
        int r0 = m0 + wm * 32 + i * 16 + g;
        #pragma unroll
        for (int f = 0; f < 8; ++f) {
            int jj = f >> 1, hf = f & 1;
            int col = n0 + wn * 64 + jj * 16 + hf * 8 + qp * 2;
            float b0 = bias[col], b1 = bias[col + 1];
            float* cc = cacc[i][f];
            if (z == 2) {
                *(half2*)&Ch2[(size_t)r0 * DIM_ + col] =
                    __floats2half2_rn(cc[0] + b0, cc[1] + b1);
                *(half2*)&Ch2[(size_t)(r0 + 8) * DIM_ + col] =
                    __floats2half2_rn(cc[2] + b0, cc[3] + b1);
            } else {
                float* Cf = (z == 0) ? Cf0 : Cf1;
                float2 v0 = {cc[0] + b0, cc[1] + b1};
                float2 v1 = {cc[2] + b0, cc[3] + b1};
                *(float2*)&Cf[(size_t)r0 * DIM_ + col] = v0;
                *(float2*)&Cf[(size_t)(r0 + 8) * DIM_ + col] = v1;
            }
        }
    }
}

// ---------------- flash attention kernel -------------------------------------
#define FLASH_SMEM (4 * 64 * LDK * 2)

__global__ __launch_bounds__(256, 1)
void flash_kernel(const __half* __restrict__ Q, const __half* __restrict__ K,
                  const __half* __restrict__ V, __half* __restrict__ O) {
    extern __shared__ __half sm[];
    __half* sK = sm;
    __half* sV = sm + 2 * 64 * LDK;

    int q0 = blockIdx.x * 128;
    int h  = blockIdx.y;
    int tid = threadIdx.x;
    int w = tid >> 5, lane = tid & 31;
    int g = lane >> 2, qp = lane & 3;
    int wm0 = w * 16;

    const __half* Qg = Q + (size_t)q0 * DIM_ + h * HD;
    const __half* Kg = K + h * HD;
    const __half* Vg = V + h * HD;

    #pragma unroll
    for (int it = 0; it < 8; ++it) {
        int slot = tid + it * 256;
        int r = slot >> 4, c = (slot & 15) << 3;
        cp_async16(&sK[r * LDK + c], Qg + (size_t)r * DIM_ + c);
    }
    cp_commit();
    cp_wait<0>();
    __syncthreads();

    unsigned qf[8][4];
    {
        unsigned base = (unsigned)__cvta_generic_to_shared(sK);
        int row = wm0 + (lane & 7) + (lane & 8);
        #pragma unroll
        for (int kk = 0; kk < 8; ++kk) {
            int col = kk * 16 + ((lane & 16) >> 1);
            ldsm_x4(qf[kk], base + (row * LDK + col) * 2);
        }
    }
    __syncthreads();

    float oacc[16][4];
    #pragma unroll
    for (int t = 0; t < 16; ++t)
        #pragma unroll
        for (int c = 0; c < 4; ++c) oacc[t][c] = 0.f;
    float mA = -1e30f, mB = -1e30f, lA = 0.f, lB = 0.f;

    #pragma unroll
    for (int it = 0; it < 4; ++it) {
        int slot = tid + it * 256;
        int r = slot >> 4, c = (slot & 15) << 3;
        cp_async16(&sK[r * LDK + c], Kg + (size_t)r * DIM_ + c);
        cp_async16(&sV[r * LDK + c], Vg + (size_t)r * DIM_ + c);
    }
    cp_commit();

    const int NCH = S_LEN / 64;
    for (int i = 0; i < NCH; ++i) {
        cp_wait<0>();
        __syncthreads();

        if (i + 1 < NCH) {
            int st = (i + 1) & 1;
            const __half* kg = Kg + (size_t)(i + 1) * 64 * DIM_;
            const __half* vg = Vg + (size_t)(i + 1) * 64 * DIM_;
            __half* dK = sK + st * 64 * LDK;
            __half* dV = sV + st * 64 * LDK;
            #pragma unroll
            for (int it = 0; it < 4; ++it) {
                int slot = tid + it * 256;
                int r = slot >> 4, c = (slot & 15) << 3;
                cp_async16(&dK[r * LDK + c], kg + (size_t)r * DIM_ + c);
                cp_async16(&dV[r * LDK + c], vg + (size_t)r * DIM_ + c);
            }
            cp_commit();
        }

        int st = i & 1;
        unsigned kbase = (unsigned)__cvta_generic_to_shared(sK + st * 64 * LDK);
        unsigned vbase = (unsigned)__cvta_generic_to_shared(sV + st * 64 * LDK);

        float sacc[8][4];
        #pragma unroll
        for (int j = 0; j < 8; ++j)
            sacc[j][0] = sacc[j][1] = sacc[j][2] = sacc[j][3] = 0.f;
        #pragma unroll
        for (int j = 0; j < 8; ++j) {
            int krow = 8 * j + (lane & 7);
            #pragma unroll
            for (int kk = 0; kk < 8; ++kk) {
                unsigned b[2];
                int kcol = 16 * kk + (lane & 8);
                ldsm_x2(b, kbase + (krow * LDK + kcol) * 2);
                mma16816(sacc[j], qf[kk], b);
            }
        }

        float cmA = -1e30f, cmB = -1e30f;
        #pragma unroll
        for (int j = 0; j < 8; ++j) {
            cmA = fmaxf(cmA, fmaxf(sacc[j][0], sacc[j][1]));
            cmB = fmaxf(cmB, fmaxf(sacc[j][2], sacc[j][3]));
        }
        cmA = fmaxf(cmA, __shfl_xor_sync(0xffffffffu, cmA, 1));
        cmA = fmaxf(cmA, __shfl_xor_sync(0xffffffffu, cmA, 2));
        cmB = fmaxf(cmB, __shfl_xor_sync(0xffffffffu, cmB, 1));
        cmB = fmaxf(cmB, __shfl_xor_sync(0xffffffffu, cmB, 2));
        float mAn = fmaxf(mA, cmA), mBn = fmaxf(mB, cmB);
        float fA = __expf(mA - mAn), fB = __expf(mB - mBn);

        float sumA = 0.f, sumB = 0.f;
        #pragma unroll
        for (int j = 0; j < 8; ++j) {
            sacc[j][0] = __expf(sacc[j][0] - mAn);
            sacc[j][1] = __expf(sacc[j][1] - mAn);
            sacc[j][2] = __expf(sacc[j][2] - mBn);
            sacc[j][3] = __expf(sacc[j][3] - mBn);
            sumA += sacc[j][0] + sacc[j][1];
            sumB += sacc[j][2] + sacc[j][3];
        }
        sumA += __shfl_xor_sync(0xffffffffu, sumA, 1);
        sumA += __shfl_xor_sync(0xffffffffu, sumA, 2);
        sumB += __shfl_xor_sync(0xffffffffu, sumB, 1);
        sumB += __shfl_xor_sync(0xffffffffu, sumB, 2);
        lA = lA * fA + sumA;
        lB = lB * fB + sumB;
        mA = mAn; mB = mBn;

        #pragma unroll
        for (int t = 0; t < 16; ++t) {
            oacc[t][0] *= fA; oacc[t][1] *= fA;
            oacc[t][2] *= fB; oacc[t][3] *= fB;
        }

        unsigned pf[4][4];
        #pragma unroll
        for (int kt = 0; kt < 4; ++kt) {
            pf[kt][0] = packh2(sacc[2 * kt][0],     sacc[2 * kt][1]);
            pf[kt][1] = packh2(sacc[2 * kt][2],     sacc[2 * kt][3]);
            pf[kt][2] = packh2(sacc[2 * kt + 1][0], sacc[2 * kt + 1][1]);
            pf[kt][3] = packh2(sacc[2 * kt + 1][2], sacc[2 * kt + 1][3]);
        }

        #pragma unroll
        for (int t = 0; t < 16; ++t) {
            #pragma unroll
            for (int kt = 0; kt < 4; ++kt) {
                unsigned b[2];
                int vrow = 16 * kt + (lane & 15);
                ldsm_x2t(b, vbase + (vrow * LDK + 8 * t) * 2);
                mma16816(oacc[t], pf[kt], b);
            }
        }
    }

    float invA = 1.f / lA, invB = 1.f / lB;
    size_t b0 = (size_t)(q0 + wm0 + g) * DIM_ + h * HD + qp * 2;
    size_t b1 = b0 + (size_t)8 * DIM_;
    #pragma unroll
    for (int t = 0; t < 16; ++t) {
        *(half2*)&O[b0 + 8 * t] =
            __floats2half2_rn(oacc[t][0] * invA, oacc[t][1] * invA);
        *(half2*)&O[b1 + 8 * t] =
            __floats2half2_rn(oacc[t][2] * invB, oacc[t][3] * invB);
    }
}

// ---------------- launch ------------------------------------------------------
extern "C" void kernel_launch(void* const* d_in, const int* in_sizes, int n_in,
                              void* d_out, int out_size) {
    const float* x   = (const float*)d_in[0];
    const float* fa  = (const float*)d_in[1];
    const float* Wq  = (const float*)d_in[2];
    const float* bq  = (const float*)d_in[3];
    const float* Wk  = (const float*)d_in[4];
    const float* bk  = (const float*)d_in[5];
    const float* Wv  = (const float*)d_in[6];
    const float* bv  = (const float*)d_in[7];
    const float* Wo  = (const float*)d_in[8];
    const float* bo  = (const float*)d_in[9];
    const float* gq  = (const float*)d_in[10];
    const float* gk  = (const float*)d_in[11];
    float* out = (float*)d_out;

    float *Qp, *Kp, *Cp, *Sn;
    __half *xh, *Wqh, *Wkh, *Wvh, *Woh, *Qh, *Kh, *Vh, *Oh;
    cudaGetSymbolAddress((void**)&Qp, g_Q);
    cudaGetSymbolAddress((void**)&Kp, g_K);
    cudaGetSymbolAddress((void**)&Cp, g_cos);
    cudaGetSymbolAddress((void**)&Sn, g_sin);
    cudaGetSymbolAddress((void**)&xh, g_xh);
    cudaGetSymbolAddress((void**)&Wqh, g_Wqh);
    cudaGetSymbolAddress((void**)&Wkh, g_Wkh);
    cudaGetSymbolAddress((void**)&Wvh, g_Wvh);
    cudaGetSymbolAddress((void**)&Woh, g_Woh);
    cudaGetSymbolAddress((void**)&Qh, g_Qh);
    cudaGetSymbolAddress((void**)&Kh, g_Kh);
    cudaGetSymbolAddress((void**)&Vh, g_Vh);
    cudaGetSymbolAddress((void**)&Oh, g_Oh);

    cudaFuncSetAttribute(flash_kernel,
                         cudaFuncAttributeMaxDynamicSharedMemorySize,
                         FLASH_SMEM);
    cudaFuncSetAttribute(gemm_mma,
                         cudaFuncAttributeMaxDynamicSharedMemorySize,
                         GEMM_SMEM);

    rope_table_kernel<<<(S_LEN * C_HALF + 255) / 256, 256>>>(fa, Cp, Sn);

    int nx4 = S_LEN * DIM_ / 4, nw4 = DIM_ * DIM_ / 4;
    f2h_kernel<<<(nx4 + 255) / 256, 256>>>(x, xh, nx4);
    w4h_kernel<<<dim3((nw4 + 255) / 256, 4), 256>>>(Wq, Wk, Wv, Wo,
                                                    Wqh, Wkh, Wvh, Woh, nw4);

    // batched QKV projections: z=0 -> Q(f32), z=1 -> K(f32), z=2 -> V(half)
    dim3 gQKV(DIM_ / 128, S_LEN / 128, 3);
    gemm_mma<<<gQKV, 256, GEMM_SMEM>>>(xh, Wqh, Wkh, Wvh, bq, bk, bv,
                                       Qp, Kp, Vh);

    // RMSNorm + RoPE -> half Q (pre-scaled by 1/sqrt(d)) and K
    rms_rope_kernel<<<S_LEN, 256>>>(Qp, Qh, gq, Cp, Sn, 0.08838834764831845f);
    rms_rope_kernel<<<S_LEN, 256>>>(Kp, Kh, gk, Cp, Sn, 1.0f);

    // fused attention
    dim3 gFlash(S_LEN / 128, NH);
    flash_kernel<<<gFlash, 256, FLASH_SMEM>>>(Qh, Kh, Vh, Oh);

    // out = O @ Wo^T + bo (fp32, z=0 path)
    dim3 gO(DIM_ / 128, S_LEN / 128, 1);
    gemm_mma<<<gO, 256, GEMM_SMEM>>>(Oh, Woh, Woh, Woh, bo, bo, bo,
                                     out, out, Vh);
}